// round 1
// baseline (speedup 1.0000x reference)
#include <cuda_runtime.h>
#include <math.h>

#define PP 4
#define BB 128
#define DD 512
#define NN 32768
#define KK 10
#define SCALE_C 10.0f
#define INV_TEMP 2.0f
#define SIM_TH 0.7f
#define KL_WEIGHT 0.4916666666666667f

// ---------------- device scratch (no allocations allowed) ----------------
__device__ float g_fn2[PP][BB];          // ||feature[p,b]||^2  (== img norms^2)
__device__ float g_txtn2[PP][BB];        // ||txt[p,b]||^2
__device__ float g_gram[2][PP][BB * BB]; // raw gram -> scaled sims (in place)
__device__ unsigned char g_negmask[NN];
__device__ float g_negsum[PP][BB];
__device__ float g_possum[PP][BB];
__device__ float g_align;

// ---------------- helpers ----------------
__device__ __forceinline__ float warpSum(float v) {
#pragma unroll
    for (int o = 16; o > 0; o >>= 1) v += __shfl_xor_sync(0xffffffffu, v, o);
    return v;
}
__device__ __forceinline__ float warpMax(float v) {
#pragma unroll
    for (int o = 16; o > 0; o >>= 1) v = fmaxf(v, __shfl_xor_sync(0xffffffffu, v, o));
    return v;
}

// ---------------- kernel 1: init mask + zero accumulators ----------------
__global__ void k_setup() {
    int gid = blockIdx.x * blockDim.x + threadIdx.x;
    if (gid < NN) g_negmask[gid] = 1;
    if (gid < PP * BB) {
        ((float*)g_negsum)[gid] = 0.0f;
        ((float*)g_possum)[gid] = 0.0f;
    }
    if (gid == 0) g_align = 0.0f;
}

// ---------------- kernel 2: scatter zeros into neg mask ----------------
__global__ void k_scatter(const int* __restrict__ position,
                          const int* __restrict__ cross) {
    int gid = blockIdx.x * blockDim.x + threadIdx.x;
    if (gid < BB * KK) {
        g_negmask[cross[gid]] = 0;
    } else if (gid < BB * KK + BB) {
        g_negmask[position[gid - BB * KK]] = 0;
    }
}

// ---------------- kernel 3: row norms for feature and txt ----------------
__global__ void k_norms(const float* __restrict__ feature,
                        const float* __restrict__ text) {
    int wid = blockIdx.x * (blockDim.x >> 5) + (threadIdx.x >> 5);
    int lane = threadIdx.x & 31;
    int type = wid / (PP * BB);
    int r = wid % (PP * BB);
    int p = r / BB, b = r % BB;
    const float4* src = (const float4*)(type == 0 ? feature + (size_t)(p * BB + b) * DD
                                                  : text + (size_t)(b * PP + p) * DD);
    float s = 0.0f;
    for (int q = lane; q < DD / 4; q += 32) {
        float4 v = src[q];
        s += v.x * v.x + v.y * v.y + v.z * v.z + v.w * v.w;
    }
    s = warpSum(s);
    if (lane == 0) {
        if (type == 0) g_fn2[p][b] = s;
        else           g_txtn2[p][b] = s;
    }
}

// ---------------- kernel 4: raw gram matrices (img & txt) ----------------
// grid (2 row-tiles, 2 col-tiles, P*2), 256 threads, 64x64 tile, 4x4 micro
__global__ __launch_bounds__(256) void k_gram(const float* __restrict__ feature,
                                              const float* __restrict__ text) {
    int mat = blockIdx.z & 1, p = blockIdx.z >> 1;
    int r0 = blockIdx.x * 64, c0 = blockIdx.y * 64;
    int t = threadIdx.x, tx = t & 15, ty = t >> 4;

    __shared__ float As[32][65];
    __shared__ float Bs[32][65];

    float acc[4][4];
#pragma unroll
    for (int i = 0; i < 4; ++i)
#pragma unroll
        for (int j = 0; j < 4; ++j) acc[i][j] = 0.0f;

    for (int k0 = 0; k0 < DD; k0 += 32) {
#pragma unroll
        for (int it = 0; it < 2; ++it) {
            int q = t + it * 256;
            int row = q >> 3, kq = q & 7;
            int ra = r0 + row, rb = c0 + row;
            const float* pa = (mat == 0) ? feature + (size_t)(p * BB + ra) * DD
                                         : text + (size_t)(ra * PP + p) * DD;
            const float* pb = (mat == 0) ? feature + (size_t)(p * BB + rb) * DD
                                         : text + (size_t)(rb * PP + p) * DD;
            float4 va = *(const float4*)(pa + k0 + kq * 4);
            float4 vb = *(const float4*)(pb + k0 + kq * 4);
            As[kq * 4 + 0][row] = va.x; As[kq * 4 + 1][row] = va.y;
            As[kq * 4 + 2][row] = va.z; As[kq * 4 + 3][row] = va.w;
            Bs[kq * 4 + 0][row] = vb.x; Bs[kq * 4 + 1][row] = vb.y;
            Bs[kq * 4 + 2][row] = vb.z; Bs[kq * 4 + 3][row] = vb.w;
        }
        __syncthreads();
#pragma unroll
        for (int k = 0; k < 32; ++k) {
            float a[4], bb[4];
#pragma unroll
            for (int i = 0; i < 4; ++i) a[i] = As[k][ty + 16 * i];
#pragma unroll
            for (int j = 0; j < 4; ++j) bb[j] = Bs[k][tx + 16 * j];
#pragma unroll
            for (int i = 0; i < 4; ++i)
#pragma unroll
                for (int j = 0; j < 4; ++j) acc[i][j] = fmaf(a[i], bb[j], acc[i][j]);
        }
        __syncthreads();
    }
    float* out = &g_gram[mat][p][0];
#pragma unroll
    for (int i = 0; i < 4; ++i)
#pragma unroll
        for (int j = 0; j < 4; ++j)
            out[(r0 + ty + 16 * i) * BB + (c0 + tx + 16 * j)] = acc[i][j];
}

// ---------------- kernel 5: scale grams into sims (in place) ----------------
__global__ void k_simscale() {
    int idx = blockIdx.x * blockDim.x + threadIdx.x; // over 2*P*B*B
    if (idx >= 2 * PP * BB * BB) return;
    int mat = idx / (PP * BB * BB);
    int rest = idx % (PP * BB * BB);
    int p = rest / (BB * BB);
    int e = rest % (BB * BB);
    int b = e >> 7, c = e & 127;
    float n2b = mat ? g_txtn2[p][b] : g_fn2[p][b];
    float n2c = mat ? g_txtn2[p][c] : g_fn2[p][c];
    float inv = 1.0f / (fmaxf(sqrtf(n2b), 1e-12f) * fmaxf(sqrtf(n2c), 1e-12f));
    g_gram[mat][p][e] *= inv * INV_TEMP;
}

// ---------------- kernel 6: align loss (per-p CTA) ----------------
__global__ __launch_bounds__(256) void k_align2() {
    int p = blockIdx.x;
    int t = threadIdx.x, warp = t >> 5, lane = t & 31;
    const float* sg = &g_gram[0][p][0];
    const float* st = &g_gram[1][p][0];

    __shared__ int valids[BB];
    __shared__ float s_r1, s_r2;
    __shared__ int s_nv;
    if (t == 0) { s_r1 = 0.0f; s_r2 = 0.0f; s_nv = 0; }

    // valid[b] = any_c (img_sim>th && txt_sim>th)
    for (int b = warp; b < BB; b += 8) {
        bool any = false;
        for (int c = lane; c < BB; c += 32)
            any = any || (sg[b * BB + c] > SIM_TH && st[b * BB + c] > SIM_TH);
        unsigned ball = __ballot_sync(0xffffffffu, any);
        if (lane == 0) valids[b] = (ball != 0u);
    }
    __syncthreads();
    if (t < BB && valids[t]) atomicAdd(&s_nv, 1);
    __syncthreads();

    for (int b = warp; b < BB; b += 8) {
        if (!valids[b]) continue;
        float mi = -1e30f, mt = -1e30f;
        for (int c = lane; c < BB; c += 32) {
            if (valids[c]) {
                mi = fmaxf(mi, sg[b * BB + c]);
                mt = fmaxf(mt, st[b * BB + c]);
            }
        }
        mi = warpMax(mi); mt = warpMax(mt);
        float zi = 0.0f, zt = 0.0f;
        for (int c = lane; c < BB; c += 32) {
            if (valids[c]) {
                zi += expf(sg[b * BB + c] - mi);
                zt += expf(st[b * BB + c] - mt);
            }
        }
        zi = warpSum(zi); zt = warpSum(zt);
        float lZi = mi + logf(zi), lZt = mt + logf(zt);
        float kl1 = 0.0f, kl2 = 0.0f;
        for (int c = lane; c < BB; c += 32) {
            if (valids[c]) {
                float li = sg[b * BB + c] - lZi;
                float lt = st[b * BB + c] - lZt;
                float pt = expf(lt), pi = expf(li);
                kl1 += pt * (lt - li);
                kl2 += pi * (li - lt);
            }
        }
        kl1 = warpSum(kl1); kl2 = warpSum(kl2);
        if (lane == 0) { atomicAdd(&s_r1, kl1); atomicAdd(&s_r2, kl2); }
    }
    __syncthreads();
    if (t == 0 && s_nv > 0) {
        float per = 0.5f * (s_r1 + s_r2) / (float)max(s_nv, 1);
        atomicAdd(&g_align, per);
    }
}

// ---------------- kernel 7: positives + pos_vid output ----------------
// one warp per (p,b); 128 blocks x 128 threads
__global__ void k_pos(const float* __restrict__ feature,
                      const float* __restrict__ centers,
                      const int* __restrict__ cross,
                      const int* __restrict__ vid,
                      float* __restrict__ out) {
    int wid = threadIdx.x >> 5, lane = threadIdx.x & 31;
    int pb = blockIdx.x * 4 + wid;
    int p = pb / BB, b = pb % BB;
    const float4* f4 = (const float4*)(feature + (size_t)(p * BB + b) * DD);
    float esum = 0.0f;
    float fb = g_fn2[p][b];
#pragma unroll
    for (int k = 0; k < KK; ++k) {
        int idx = cross[b * KK + k];
        const float4* c4 = (const float4*)(centers + ((size_t)p * NN + idx) * DD);
        float dot = 0.0f, cn = 0.0f;
        for (int q = lane; q < DD / 4; q += 32) {
            float4 cv = c4[q], fv = f4[q];
            dot += cv.x * fv.x + cv.y * fv.y + cv.z * fv.z + cv.w * fv.w;
            cn += cv.x * cv.x + cv.y * cv.y + cv.z * cv.z + cv.w * cv.w;
        }
        dot = warpSum(dot); cn = warpSum(cn);
        float d2 = fb + cn - 2.0f * dot;
        float dist = sqrtf(fmaxf(d2, 1e-12f));
        esum += expf(-SCALE_C * dist);
        if (p == 0 && lane == 0) out[3 + b * KK + k] = (float)vid[idx];
    }
    if (lane == 0) g_possum[p][b] = esum;
}

// ---------------- kernel 8: fused negative GEMM + epilogue ----------------
// grid (N/128, P), 256 threads, 128x128 tile, 8x8 micro (strided by 16)
__global__ __launch_bounds__(256, 2) void k_neg(const float* __restrict__ feature,
                                                const float* __restrict__ centers) {
    int p = blockIdx.y;
    int n0 = blockIdx.x * 128;
    int t = threadIdx.x, tx = t & 15, ty = t >> 4;

    __shared__ float As[32][129];
    __shared__ float Bs[32][129];
    __shared__ float rsum[BB];
    __shared__ float fn2s[BB];

    if (t < BB) { rsum[t] = 0.0f; fn2s[t] = g_fn2[p][t]; }

    const float* featp = feature + (size_t)p * BB * DD;
    const float* cenp = centers + ((size_t)p * NN + n0) * DD;

    float acc[8][8];
    float cacc[8];
#pragma unroll
    for (int i = 0; i < 8; ++i) {
        cacc[i] = 0.0f;
#pragma unroll
        for (int j = 0; j < 8; ++j) acc[i][j] = 0.0f;
    }

    for (int k0 = 0; k0 < DD; k0 += 32) {
        __syncthreads(); // protects As/Bs reuse (and covers rsum/fn2s init first pass)
#pragma unroll
        for (int it = 0; it < 4; ++it) {
            int q = t + it * 256;
            int row = q >> 3, kq = q & 7;
            float4 va = *(const float4*)(featp + (size_t)row * DD + k0 + kq * 4);
            float4 vb = *(const float4*)(cenp + (size_t)row * DD + k0 + kq * 4);
            As[kq * 4 + 0][row] = va.x; As[kq * 4 + 1][row] = va.y;
            As[kq * 4 + 2][row] = va.z; As[kq * 4 + 3][row] = va.w;
            Bs[kq * 4 + 0][row] = vb.x; Bs[kq * 4 + 1][row] = vb.y;
            Bs[kq * 4 + 2][row] = vb.z; Bs[kq * 4 + 3][row] = vb.w;
        }
        __syncthreads();
#pragma unroll
        for (int k = 0; k < 32; ++k) {
            float a[8], bb[8];
#pragma unroll
            for (int i = 0; i < 8; ++i) a[i] = As[k][ty + 16 * i];
#pragma unroll
            for (int j = 0; j < 8; ++j) bb[j] = Bs[k][tx + 16 * j];
#pragma unroll
            for (int j = 0; j < 8; ++j) cacc[j] = fmaf(bb[j], bb[j], cacc[j]);
#pragma unroll
            for (int i = 0; i < 8; ++i)
#pragma unroll
                for (int j = 0; j < 8; ++j) acc[i][j] = fmaf(a[i], bb[j], acc[i][j]);
        }
    }
    __syncthreads();

    float mfl[8];
#pragma unroll
    for (int j = 0; j < 8; ++j)
        mfl[j] = g_negmask[n0 + tx + 16 * j] ? 1.0f : 0.0f;

#pragma unroll
    for (int i = 0; i < 8; ++i) {
        int b = ty + 16 * i;
        float fb = fn2s[b];
        float s = 0.0f;
#pragma unroll
        for (int j = 0; j < 8; ++j) {
            float d2 = fb + cacc[j] - 2.0f * acc[i][j];
            float dist = sqrtf(fmaxf(d2, 1e-12f));
            s += mfl[j] * expf(-SCALE_C * dist);
        }
        atomicAdd(&rsum[b], s);
    }
    __syncthreads();
    if (t < BB) atomicAdd(&g_negsum[p][t], rsum[t]);
}

// ---------------- kernel 9: final reduction -> out[0..2] ----------------
__global__ void k_final(float* __restrict__ out) {
    __shared__ float mat[PP][BB];
    __shared__ float lp[PP];
    int t = threadIdx.x; // 128
#pragma unroll
    for (int p = 0; p < PP; ++p) {
        float y = logf(g_negsum[p][t]);
        float x = logf(g_possum[p][t]);
        mat[p][t] = y - x;
    }
    __syncthreads();
    if (t < PP) {
        float s = 0.0f;
        for (int b = 0; b < BB; ++b) s += mat[t][b];
        s /= (float)BB;
        if (s != s) s = 0.0f; // isnan
        lp[t] = s;
    }
    __syncthreads();
    if (t == 0) {
        float c = (lp[0] + lp[1] + lp[2] + lp[3]) / (float)PP;
        float a = g_align;
        out[0] = c + KL_WEIGHT * a;
        out[1] = c;
        out[2] = a;
    }
}

// ---------------- launch ----------------
extern "C" void kernel_launch(void* const* d_in, const int* in_sizes, int n_in,
                              void* d_out, int out_size) {
    const float* feature = (const float*)d_in[0];
    const float* text = (const float*)d_in[1];
    const float* centers = (const float*)d_in[2];
    const int* position = (const int*)d_in[3];
    const int* cross = (const int*)d_in[4];
    const int* vid = (const int*)d_in[5];
    float* out = (float*)d_out;

    k_setup<<<NN / 256, 256>>>();
    k_scatter<<<2, 1024>>>(position, cross);
    k_norms<<<(2 * PP * BB) / 4, 128>>>(feature, text);
    k_gram<<<dim3(2, 2, PP * 2), 256>>>(feature, text);
    k_simscale<<<(2 * PP * BB * BB) / 256, 256>>>();
    k_align2<<<PP, 256>>>();
    k_pos<<<(PP * BB) / 4, 128>>>(feature, centers, cross, vid, out);
    k_neg<<<dim3(NN / 128, PP), 256>>>(feature, centers);
    k_final<<<1, 128>>>(out);
}

// round 14
// speedup vs baseline: 1.8975x; 1.8975x over previous
#include <cuda_runtime.h>
#include <math.h>
#include <stdint.h>

#define PP 4
#define BB 128
#define DD 512
#define NN 32768
#define KK 10
#define SCALE_C 10.0f
#define INV_TEMP 2.0f
#define SIM_TH 0.7f
#define KL_WEIGHT 0.4916666666666667f

// ---------------- device scratch (no allocations allowed) ----------------
__device__ float g_fn2[PP][BB];          // ||feature[p,b]||^2
__device__ float g_txtn2[PP][BB];        // ||txt[p,b]||^2
__device__ float g_gram[2][PP][BB * BB]; // scaled sims
__device__ unsigned char g_negmask[NN];
__device__ float g_negsum[PP][BB];
__device__ float g_possum[PP][BB];
__device__ float g_align;

// ---------------- helpers ----------------
__device__ __forceinline__ float warpSum(float v) {
#pragma unroll
    for (int o = 16; o > 0; o >>= 1) v += __shfl_xor_sync(0xffffffffu, v, o);
    return v;
}
__device__ __forceinline__ float warpMax(float v) {
#pragma unroll
    for (int o = 16; o > 0; o >>= 1) v = fmaxf(v, __shfl_xor_sync(0xffffffffu, v, o));
    return v;
}
__device__ __forceinline__ uint32_t f2tf32(float f) {
    uint32_t r;
    asm("cvt.rna.tf32.f32 %0, %1;" : "=r"(r) : "f"(f));
    return r;
}
__device__ __forceinline__ void mma_tf32(float c[4], const uint32_t a[4],
                                         const uint32_t b[2]) {
    asm volatile(
        "mma.sync.aligned.m16n8k8.row.col.f32.tf32.tf32.f32 "
        "{%0,%1,%2,%3}, {%4,%5,%6,%7}, {%8,%9}, {%0,%1,%2,%3};"
        : "+f"(c[0]), "+f"(c[1]), "+f"(c[2]), "+f"(c[3])
        : "r"(a[0]), "r"(a[1]), "r"(a[2]), "r"(a[3]), "r"(b[0]), "r"(b[1]));
}

// ---------------- kernel 1: init mask + zero accumulators ----------------
__global__ void k_setup() {
    int gid = blockIdx.x * blockDim.x + threadIdx.x;
    if (gid < NN) g_negmask[gid] = 1;
    if (gid < PP * BB) {
        ((float*)g_negsum)[gid] = 0.0f;
        ((float*)g_possum)[gid] = 0.0f;
    }
    if (gid == 0) g_align = 0.0f;
}

// ---------------- kernel 2: scatter zeros into neg mask ----------------
__global__ void k_scatter(const int* __restrict__ position,
                          const int* __restrict__ cross) {
    int gid = blockIdx.x * blockDim.x + threadIdx.x;
    if (gid < BB * KK) {
        g_negmask[cross[gid]] = 0;
    } else if (gid < BB * KK + BB) {
        g_negmask[position[gid - BB * KK]] = 0;
    }
}

// ---------------- kernel 3: row norms for feature and txt ----------------
__global__ void k_norms(const float* __restrict__ feature,
                        const float* __restrict__ text) {
    int wid = blockIdx.x * (blockDim.x >> 5) + (threadIdx.x >> 5);
    int lane = threadIdx.x & 31;
    int type = wid / (PP * BB);
    int r = wid % (PP * BB);
    int p = r / BB, b = r % BB;
    const float4* src = (const float4*)(type == 0 ? feature + (size_t)(p * BB + b) * DD
                                                  : text + (size_t)(b * PP + p) * DD);
    float s = 0.0f;
    for (int q = lane; q < DD / 4; q += 32) {
        float4 v = src[q];
        s += v.x * v.x + v.y * v.y + v.z * v.z + v.w * v.w;
    }
    s = warpSum(s);
    if (lane == 0) {
        if (type == 0) g_fn2[p][b] = s;
        else           g_txtn2[p][b] = s;
    }
}

// ---------------- kernel 4: tf32-MMA gram + normalize (8 CTAs) ----------------
// CTA = full 128x128 gram for (mat, p). 256 thr = 8 warps as 2(M) x 4(N).
__global__ __launch_bounds__(256, 2) void k_gram_mma(const float* __restrict__ feature,
                                                     const float* __restrict__ text) {
    int mat = blockIdx.x & 1, p = blockIdx.x >> 1;
    int t = threadIdx.x, lane = t & 31, wid = t >> 5;
    int wm = wid >> 2, wn = wid & 3;

    __shared__ uint32_t Xs[32][133];
    __shared__ float invn[BB];

    if (t < BB) {
        float n2 = mat ? g_txtn2[p][t] : g_fn2[p][t];
        invn[t] = 1.0f / fmaxf(sqrtf(n2), 1e-12f);
    }

    int row = t >> 1;
    int kh = (t & 1) * 16;
    const float* src = mat ? text + (size_t)(row * PP + p) * DD + kh
                           : feature + (size_t)(p * BB + row) * DD + kh;

    float acc[4][4][4];
#pragma unroll
    for (int i = 0; i < 4; ++i)
#pragma unroll
        for (int j = 0; j < 4; ++j)
#pragma unroll
            for (int q = 0; q < 4; ++q) acc[i][j][q] = 0.0f;

    for (int c = 0; c < DD / 32; ++c) {
        float4 v[4];
#pragma unroll
        for (int q = 0; q < 4; ++q)
            v[q] = *(const float4*)(src + c * 32 + q * 4);
        __syncthreads();
#pragma unroll
        for (int q = 0; q < 4; ++q) {
            Xs[kh + q * 4 + 0][row] = f2tf32(v[q].x);
            Xs[kh + q * 4 + 1][row] = f2tf32(v[q].y);
            Xs[kh + q * 4 + 2][row] = f2tf32(v[q].z);
            Xs[kh + q * 4 + 3][row] = f2tf32(v[q].w);
        }
        __syncthreads();
#pragma unroll
        for (int ks = 0; ks < 4; ++ks) {
            int kb = ks * 8;
            uint32_t a[4][4], b[4][2];
#pragma unroll
            for (int mt = 0; mt < 4; ++mt) {
                int m = wm * 64 + mt * 16 + (lane >> 2);
                a[mt][0] = Xs[kb + (lane & 3)][m];
                a[mt][1] = Xs[kb + (lane & 3)][m + 8];
                a[mt][2] = Xs[kb + 4 + (lane & 3)][m];
                a[mt][3] = Xs[kb + 4 + (lane & 3)][m + 8];
            }
#pragma unroll
            for (int nt = 0; nt < 4; ++nt) {
                int n = wn * 32 + nt * 8 + (lane >> 2);
                b[nt][0] = Xs[kb + (lane & 3)][n];
                b[nt][1] = Xs[kb + 4 + (lane & 3)][n];
            }
#pragma unroll
            for (int mt = 0; mt < 4; ++mt)
#pragma unroll
                for (int nt = 0; nt < 4; ++nt) mma_tf32(acc[mt][nt], a[mt], b[nt]);
        }
    }
    __syncthreads();

    float* out = &g_gram[mat][p][0];
#pragma unroll
    for (int mt = 0; mt < 4; ++mt) {
        int r0 = wm * 64 + mt * 16 + (lane >> 2);
#pragma unroll
        for (int nt = 0; nt < 4; ++nt) {
            int n = wn * 32 + nt * 8 + 2 * (lane & 3);
#pragma unroll
            for (int cc = 0; cc < 2; ++cc) {
                out[r0 * BB + n + cc] = acc[mt][nt][cc] * invn[r0] * invn[n + cc] * INV_TEMP;
                out[(r0 + 8) * BB + n + cc] =
                    acc[mt][nt][2 + cc] * invn[r0 + 8] * invn[n + cc] * INV_TEMP;
            }
        }
    }
}

// ---------------- kernel 5: align loss (per-p CTA) ----------------
__global__ __launch_bounds__(256) void k_align2() {
    int p = blockIdx.x;
    int t = threadIdx.x, warp = t >> 5, lane = t & 31;
    const float* sg = &g_gram[0][p][0];
    const float* st = &g_gram[1][p][0];

    __shared__ int valids[BB];
    __shared__ float s_r1, s_r2;
    __shared__ int s_nv;
    if (t == 0) { s_r1 = 0.0f; s_r2 = 0.0f; s_nv = 0; }

    for (int b = warp; b < BB; b += 8) {
        bool any = false;
        for (int c = lane; c < BB; c += 32)
            any = any || (sg[b * BB + c] > SIM_TH && st[b * BB + c] > SIM_TH);
        unsigned ball = __ballot_sync(0xffffffffu, any);
        if (lane == 0) valids[b] = (ball != 0u);
    }
    __syncthreads();
    if (t < BB && valids[t]) atomicAdd(&s_nv, 1);
    __syncthreads();

    for (int b = warp; b < BB; b += 8) {
        if (!valids[b]) continue;
        float mi = -1e30f, mt = -1e30f;
        for (int c = lane; c < BB; c += 32) {
            if (valids[c]) {
                mi = fmaxf(mi, sg[b * BB + c]);
                mt = fmaxf(mt, st[b * BB + c]);
            }
        }
        mi = warpMax(mi); mt = warpMax(mt);
        float zi = 0.0f, zt = 0.0f;
        for (int c = lane; c < BB; c += 32) {
            if (valids[c]) {
                zi += expf(sg[b * BB + c] - mi);
                zt += expf(st[b * BB + c] - mt);
            }
        }
        zi = warpSum(zi); zt = warpSum(zt);
        float lZi = mi + logf(zi), lZt = mt + logf(zt);
        float kl1 = 0.0f, kl2 = 0.0f;
        for (int c = lane; c < BB; c += 32) {
            if (valids[c]) {
                float li = sg[b * BB + c] - lZi;
                float lt = st[b * BB + c] - lZt;
                float pt = expf(lt), pi = expf(li);
                kl1 += pt * (lt - li);
                kl2 += pi * (li - lt);
            }
        }
        kl1 = warpSum(kl1); kl2 = warpSum(kl2);
        if (lane == 0) { atomicAdd(&s_r1, kl1); atomicAdd(&s_r2, kl2); }
    }
    __syncthreads();
    if (t == 0 && s_nv > 0) {
        float per = 0.5f * (s_r1 + s_r2) / (float)max(s_nv, 1);
        atomicAdd(&g_align, per);
    }
}

// ---------------- kernel 6: positives + pos_vid output ----------------
__global__ void k_pos(const float* __restrict__ feature,
                      const float* __restrict__ centers,
                      const int* __restrict__ cross,
                      const int* __restrict__ vid,
                      float* __restrict__ out) {
    int wid = threadIdx.x >> 5, lane = threadIdx.x & 31;
    int pb = blockIdx.x * 4 + wid;
    int p = pb / BB, b = pb % BB;
    const float4* f4 = (const float4*)(feature + (size_t)(p * BB + b) * DD);
    float esum = 0.0f;
    float fb = g_fn2[p][b];
#pragma unroll
    for (int k = 0; k < KK; ++k) {
        int idx = cross[b * KK + k];
        const float4* c4 = (const float4*)(centers + ((size_t)p * NN + idx) * DD);
        float dot = 0.0f, cn = 0.0f;
        for (int q = lane; q < DD / 4; q += 32) {
            float4 cv = c4[q], fv = f4[q];
            dot += cv.x * fv.x + cv.y * fv.y + cv.z * fv.z + cv.w * fv.w;
            cn += cv.x * cv.x + cv.y * cv.y + cv.z * cv.z + cv.w * cv.w;
        }
        dot = warpSum(dot); cn = warpSum(cn);
        float d2 = fb + cn - 2.0f * dot;
        float dist = sqrtf(fmaxf(d2, 1e-12f));
        esum += expf(-SCALE_C * dist);
        if (p == 0 && lane == 0) out[3 + b * KK + k] = (float)vid[idx];
    }
    if (lane == 0) g_possum[p][b] = esum;
}

// ---------------- kernel 7: tf32-MMA negative GEMM + fused epilogue ----------
// grid (N/128, P), 256 thr = 8 warps as 2(M) x 4(N); CTA tile 128x128, K=512.
__global__ __launch_bounds__(256, 2) void k_neg_mma(const float* __restrict__ feature,
                                                    const float* __restrict__ centers) {
    int p = blockIdx.y;
    int n0 = blockIdx.x * 128;
    int t = threadIdx.x, lane = t & 31, wid = t >> 5;
    int wm = wid >> 2, wn = wid & 3;

    __shared__ uint32_t As[32][133];
    __shared__ uint32_t Bs[32][133];
    __shared__ float fn2s[BB], cn2s[BB], maskf[BB], rsum[BB];

    if (t < BB) {
        fn2s[t] = g_fn2[p][t];
        maskf[t] = __ldg(&g_negmask[n0 + t]) ? 1.0f : 0.0f;
        rsum[t] = 0.0f;
    }

    int row = t >> 1;
    int kh = (t & 1) * 16;
    const float* Aptr = feature + (size_t)(p * BB + row) * DD + kh;
    const float* Bptr = centers + ((size_t)p * NN + n0 + row) * DD + kh;

    float acc[4][4][4];
#pragma unroll
    for (int i = 0; i < 4; ++i)
#pragma unroll
        for (int j = 0; j < 4; ++j)
#pragma unroll
            for (int q = 0; q < 4; ++q) acc[i][j][q] = 0.0f;

    float cn2p = 0.0f;

    for (int c = 0; c < DD / 32; ++c) {
        float4 av[4], bv[4];
#pragma unroll
        for (int q = 0; q < 4; ++q) {
            av[q] = *(const float4*)(Aptr + c * 32 + q * 4);
            bv[q] = *(const float4*)(Bptr + c * 32 + q * 4);
        }
#pragma unroll
        for (int q = 0; q < 4; ++q)
            cn2p += bv[q].x * bv[q].x + bv[q].y * bv[q].y +
                    bv[q].z * bv[q].z + bv[q].w * bv[q].w;
        __syncthreads();
#pragma unroll
        for (int q = 0; q < 4; ++q) {
            As[kh + q * 4 + 0][row] = f2tf32(av[q].x);
            As[kh + q * 4 + 1][row] = f2tf32(av[q].y);
            As[kh + q * 4 + 2][row] = f2tf32(av[q].z);
            As[kh + q * 4 + 3][row] = f2tf32(av[q].w);
            Bs[kh + q * 4 + 0][row] = f2tf32(bv[q].x);
            Bs[kh + q * 4 + 1][row] = f2tf32(bv[q].y);
            Bs[kh + q * 4 + 2][row] = f2tf32(bv[q].z);
            Bs[kh + q * 4 + 3][row] = f2tf32(bv[q].w);
        }
        __syncthreads();
#pragma unroll
        for (int ks = 0; ks < 4; ++ks) {
            int kb = ks * 8;
            uint32_t a[4][4], b[4][2];
#pragma unroll
            for (int mt = 0; mt < 4; ++mt) {
                int m = wm * 64 + mt * 16 + (lane >> 2);
                a[mt][0] = As[kb + (lane & 3)][m];
                a[mt][1] = As[kb + (lane & 3)][m + 8];
                a[mt][2] = As[kb + 4 + (lane & 3)][m];
                a[mt][3] = As[kb + 4 + (lane & 3)][m + 8];
            }
#pragma unroll
            for (int nt = 0; nt < 4; ++nt) {
                int n = wn * 32 + nt * 8 + (lane >> 2);
                b[nt][0] = Bs[kb + (lane & 3)][n];
                b[nt][1] = Bs[kb + 4 + (lane & 3)][n];
            }
#pragma unroll
            for (int mt = 0; mt < 4; ++mt)
#pragma unroll
                for (int nt = 0; nt < 4; ++nt) mma_tf32(acc[mt][nt], a[mt], b[nt]);
        }
    }

    // combine per-thread cn2 halves (two threads per center row)
    if ((t & 1) == 0) cn2s[row] = cn2p;
    __syncthreads();
    if (t & 1) cn2s[row] += cn2p;
    __syncthreads();

    // epilogue: dist -> exp -> masked row sums
#pragma unroll
    for (int mt = 0; mt < 4; ++mt) {
        int r0 = wm * 64 + mt * 16 + (lane >> 2);
        float fb0 = fn2s[r0], fb1 = fn2s[r0 + 8];
        float s0 = 0.0f, s1 = 0.0f;
#pragma unroll
        for (int nt = 0; nt < 4; ++nt) {
            int n = wn * 32 + nt * 8 + 2 * (lane & 3);
#pragma unroll
            for (int cc = 0; cc < 2; ++cc) {
                int nn = n + cc;
                float mk = maskf[nn];
                float cn = cn2s[nn];
                float d0 = fb0 + cn - 2.0f * acc[mt][nt][cc];
                float d1 = fb1 + cn - 2.0f * acc[mt][nt][2 + cc];
                s0 += mk * expf(-SCALE_C * sqrtf(fmaxf(d0, 1e-12f)));
                s1 += mk * expf(-SCALE_C * sqrtf(fmaxf(d1, 1e-12f)));
            }
        }
        s0 += __shfl_xor_sync(0xffffffffu, s0, 1);
        s0 += __shfl_xor_sync(0xffffffffu, s0, 2);
        s1 += __shfl_xor_sync(0xffffffffu, s1, 1);
        s1 += __shfl_xor_sync(0xffffffffu, s1, 2);
        if ((lane & 3) == 0) {
            atomicAdd(&rsum[r0], s0);
            atomicAdd(&rsum[r0 + 8], s1);
        }
    }
    __syncthreads();
    if (t < BB) atomicAdd(&g_negsum[p][t], rsum[t]);
}

// ---------------- kernel 8: final reduction -> out[0..2] ----------------
__global__ void k_final(float* __restrict__ out) {
    __shared__ float mat[PP][BB];
    __shared__ float lp[PP];
    int t = threadIdx.x; // 128
#pragma unroll
    for (int p = 0; p < PP; ++p) {
        float y = logf(g_negsum[p][t]);
        float x = logf(g_possum[p][t]);
        mat[p][t] = y - x;
    }
    __syncthreads();
    if (t < PP) {
        float s = 0.0f;
        for (int b = 0; b < BB; ++b) s += mat[t][b];
        s /= (float)BB;
        if (s != s) s = 0.0f; // isnan
        lp[t] = s;
    }
    __syncthreads();
    if (t == 0) {
        float c = (lp[0] + lp[1] + lp[2] + lp[3]) / (float)PP;
        float a = g_align;
        out[0] = c + KL_WEIGHT * a;
        out[1] = c;
        out[2] = a;
    }
}

// ---------------- launch ----------------
extern "C" void kernel_launch(void* const* d_in, const int* in_sizes, int n_in,
                              void* d_out, int out_size) {
    const float* feature = (const float*)d_in[0];
    const float* text = (const float*)d_in[1];
    const float* centers = (const float*)d_in[2];
    const int* position = (const int*)d_in[3];
    const int* cross = (const int*)d_in[4];
    const int* vid = (const int*)d_in[5];
    float* out = (float*)d_out;

    k_setup<<<NN / 256, 256>>>();
    k_scatter<<<2, 1024>>>(position, cross);
    k_norms<<<(2 * PP * BB) / 4, 128>>>(feature, text);
    k_gram_mma<<<PP * 2, 256>>>(feature, text);
    k_align2<<<PP, 256>>>();
    k_pos<<<(PP * BB) / 4, 128>>>(feature, centers, cross, vid, out);
    k_neg_mma<<<dim3(NN / 128, PP), 256>>>(feature, centers);
    k_final<<<1, 128>>>(out);
}